// round 7
// baseline (speedup 1.0000x reference)
#include <cuda_runtime.h>
#include <cuda_fp16.h>
#include <cstdint>

#define B_ROWS  4096
#define IN_DIM  2048
#define OUT_DIM 2048

// ---------------------------------------------------------------------------
// Device scratch (static globals — no runtime allocation allowed)
// ---------------------------------------------------------------------------
__device__ __half g_Xh [(size_t)B_ROWS  * IN_DIM];   // half(clip(x,±5))        16MB
__device__ __half g_Wth[(size_t)OUT_DIM * IN_DIM];   // half(Ws+Wm+Wf)           8MB
__device__ __half g_Ph [(size_t)B_ROWS  * OUT_DIM];  // half(pre_act)           16MB

// ---------------------------------------------------------------------------
// PTX helpers (family-safe: cp.async, ldmatrix, mma.sync)
// ---------------------------------------------------------------------------
__device__ __forceinline__ uint32_t smem_u32(const void* p) {
    uint32_t a;
    asm("{ .reg .u64 t; cvta.to.shared.u64 t, %1; cvt.u32.u64 %0, t; }"
        : "=r"(a) : "l"(p));
    return a;
}

__device__ __forceinline__ uint32_t h2_bits(__half2 h) {
    return *reinterpret_cast<uint32_t*>(&h);
}

__device__ __forceinline__ void cp_async16(uint32_t dst, const void* src) {
    asm volatile("cp.async.cg.shared.global [%0], [%1], 16;"
                 :: "r"(dst), "l"(src));
}
#define CP_COMMIT() asm volatile("cp.async.commit_group;" ::: "memory")
#define CP_WAIT(n)  asm volatile("cp.async.wait_group %0;" :: "n"(n) : "memory")

#define LDSM_X4(r0, r1, r2, r3, addr)                                         \
    asm volatile("ldmatrix.sync.aligned.m8n8.x4.shared.b16 {%0,%1,%2,%3}, [%4];" \
                 : "=r"(r0), "=r"(r1), "=r"(r2), "=r"(r3) : "r"(addr))

#define MMA_16816(d0, d1, d2, d3, a0, a1, a2, a3, b0, b1)                     \
    asm volatile("mma.sync.aligned.m16n8k16.row.col.f32.f16.f16.f32 "         \
                 "{%0,%1,%2,%3}, {%4,%5,%6,%7}, {%8,%9}, {%0,%1,%2,%3};"      \
                 : "+f"(d0), "+f"(d1), "+f"(d2), "+f"(d3)                     \
                 : "r"(a0), "r"(a1), "r"(a2), "r"(a3), "r"(b0), "r"(b1))

// ---------------------------------------------------------------------------
// Fused prepass. Heavy W-fold blocks first (better tail behavior):
//   blocks [0, 2048)    : fold W_slow+W_medium+W_fast -> fp16
//   blocks [2048, 6144) : convert x (clip ±5 -> fp16)
// 8 elems/thread, 16B loads/stores.
// ---------------------------------------------------------------------------
__global__ void prep_kernel(const float4* __restrict__ x,
                            const float4* __restrict__ ws,
                            const float4* __restrict__ wm,
                            const float4* __restrict__ wf) {
    if (blockIdx.x < 2048) {
        int i = blockIdx.x * blockDim.x + threadIdx.x;
        float4 s0 = ws[2 * i], s1 = ws[2 * i + 1];
        float4 m0 = wm[2 * i], m1 = wm[2 * i + 1];
        float4 f0 = wf[2 * i], f1 = wf[2 * i + 1];
        uint4 ot;
        ot.x = h2_bits(__floats2half2_rn(s0.x + m0.x + f0.x, s0.y + m0.y + f0.y));
        ot.y = h2_bits(__floats2half2_rn(s0.z + m0.z + f0.z, s0.w + m0.w + f0.w));
        ot.z = h2_bits(__floats2half2_rn(s1.x + m1.x + f1.x, s1.y + m1.y + f1.y));
        ot.w = h2_bits(__floats2half2_rn(s1.z + m1.z + f1.z, s1.w + m1.w + f1.w));
        reinterpret_cast<uint4*>(g_Wth)[i] = ot;
    } else {
        int i = (blockIdx.x - 2048) * blockDim.x + threadIdx.x;
        float4 a = x[2 * i], b = x[2 * i + 1];
        a.x = fminf(fmaxf(a.x, -5.0f), 5.0f);  a.y = fminf(fmaxf(a.y, -5.0f), 5.0f);
        a.z = fminf(fmaxf(a.z, -5.0f), 5.0f);  a.w = fminf(fmaxf(a.w, -5.0f), 5.0f);
        b.x = fminf(fmaxf(b.x, -5.0f), 5.0f);  b.y = fminf(fmaxf(b.y, -5.0f), 5.0f);
        b.z = fminf(fmaxf(b.z, -5.0f), 5.0f);  b.w = fminf(fmaxf(b.w, -5.0f), 5.0f);
        uint4 o;
        o.x = h2_bits(__floats2half2_rn(a.x, a.y));
        o.y = h2_bits(__floats2half2_rn(a.z, a.w));
        o.z = h2_bits(__floats2half2_rn(b.x, b.y));
        o.w = h2_bits(__floats2half2_rn(b.z, b.w));
        reinterpret_cast<uint4*>(g_Xh)[i] = o;
    }
}

// ---------------------------------------------------------------------------
// fp16 mma.sync GEMM.  P[m,n] = sum_k A[m,k] * Wt[n,k]   (both K-major)
// CTA tile 128x128xK64, 8 warps as 2(m) x 4(n), warp tile 64x32.
// 3-stage cp.async pipeline (prefetch distance 2). Epilogue stores fp16 P.
// ---------------------------------------------------------------------------
constexpr int BM = 128, BN = 128, BK = 64, STAGES = 3;
constexpr int ASTRIDE = 72;                       // halves per smem row (144B, CF for ldmatrix)
constexpr int TILE_HALVES = 128 * ASTRIDE;        // 9216 (A or B tile)
constexpr int STG_HALVES  = 2 * TILE_HALVES;      // 18432
constexpr int SMEM_GEMM_BYTES = STAGES * STG_HALVES * 2;  // 110592
constexpr int NCHUNK = IN_DIM / BK;               // 32

__global__ __launch_bounds__(256, 2)
void gemm_fp16_kernel() {
    extern __shared__ __half sm[];
    const int tid  = threadIdx.x;
    const int wid  = tid >> 5;
    const int lane = tid & 31;
    const int bm = blockIdx.x * BM;
    const int bn = blockIdx.y * BN;
    const __half* __restrict__ W = g_Wth;

    const int wmBase = (wid & 1) * 64;   // warp m offset (2 warps)
    const int wnBase = (wid >> 1) * 32;  // warp n offset (4 warps)

    const uint32_t sbase = smem_u32(sm);

    // Per-thread load slots: 128 rows x 128B; 2 threads/row, 4x16B chunks each.
    const int lrow = tid >> 1;           // 0..127
    const int lq   = tid & 1;            // half-row selector (4 chunks each)
    const __half* gA = g_Xh + (size_t)(bm + lrow) * IN_DIM + lq * 32;
    const __half* gB = W    + (size_t)(bn + lrow) * IN_DIM + lq * 32;
    const uint32_t dA = (uint32_t)(lrow * ASTRIDE + lq * 32) * 2;
    const uint32_t dB = dA + TILE_HALVES * 2;

    auto load_stage = [&](int stage, int chunk) {
        const uint32_t sb = sbase + (uint32_t)stage * STG_HALVES * 2;
        const size_t ko = (size_t)chunk * BK;
#pragma unroll
        for (int j = 0; j < 4; j++) {
            cp_async16(sb + dA + j * 16, gA + ko + j * 8);
            cp_async16(sb + dB + j * 16, gB + ko + j * 8);
        }
    };

    // ldmatrix source addresses (lane-dependent, stage-relative)
    const int aRow = wmBase + (lane & 15);
    const int aCol = (lane >> 4) * 8;
    const int bRow = wnBase + (lane & 15);
    const uint32_t aOffBase = (uint32_t)(aRow * ASTRIDE + aCol) * 2;
    const uint32_t bOffBase = (uint32_t)(bRow * ASTRIDE + aCol) * 2 + TILE_HALVES * 2;

    float acc[4][4][4];
#pragma unroll
    for (int i = 0; i < 4; i++)
#pragma unroll
        for (int j = 0; j < 4; j++)
#pragma unroll
            for (int q = 0; q < 4; q++) acc[i][j][q] = 0.0f;

    // Prologue: chunks 0,1 into stages 0,1
#pragma unroll
    for (int s = 0; s < STAGES - 1; s++) {
        load_stage(s, s);
        CP_COMMIT();
    }

#pragma unroll 1
    for (int k = 0; k < NCHUNK; k++) {
        CP_WAIT(1);
        __syncthreads();

        const int kn = k + STAGES - 1;
        if (kn < NCHUNK) load_stage((kn >= 3 ? kn - 3 : kn) % 3 == 0 ? (kn % 3) : (kn % 3), kn);
        CP_COMMIT();

        const uint32_t sb = sbase + (uint32_t)(k % 3) * STG_HALVES * 2;

#pragma unroll
        for (int kk = 0; kk < 4; kk++) {
            const uint32_t kOff = (uint32_t)(kk * 16) * 2;
            uint32_t a[4][4];
#pragma unroll
            for (int i = 0; i < 4; i++) {
                LDSM_X4(a[i][0], a[i][1], a[i][2], a[i][3],
                        sb + aOffBase + kOff + (uint32_t)(i * 16 * ASTRIDE) * 2);
            }
            uint32_t b[2][4];
#pragma unroll
            for (int jj = 0; jj < 2; jj++) {
                LDSM_X4(b[jj][0], b[jj][1], b[jj][2], b[jj][3],
                        sb + bOffBase + kOff + (uint32_t)(jj * 16 * ASTRIDE) * 2);
            }
#pragma unroll
            for (int i = 0; i < 4; i++) {
#pragma unroll
                for (int jj = 0; jj < 2; jj++) {
                    MMA_16816(acc[i][2 * jj][0], acc[i][2 * jj][1],
                              acc[i][2 * jj][2], acc[i][2 * jj][3],
                              a[i][0], a[i][1], a[i][2], a[i][3],
                              b[jj][0], b[jj][2]);
                    MMA_16816(acc[i][2 * jj + 1][0], acc[i][2 * jj + 1][1],
                              acc[i][2 * jj + 1][2], acc[i][2 * jj + 1][3],
                              a[i][0], a[i][1], a[i][2], a[i][3],
                              b[jj][1], b[jj][3]);
                }
            }
        }
    }

    // Epilogue: pack accumulators to fp16, 32-bit stores (cols even-aligned)
    const int er = lane >> 2;
    const int ec = (lane & 3) * 2;
#pragma unroll
    for (int i = 0; i < 4; i++) {
        const int row0 = bm + wmBase + i * 16 + er;
#pragma unroll
        for (int j = 0; j < 4; j++) {
            const int col = bn + wnBase + j * 8 + ec;
            uint32_t v0 = h2_bits(__floats2half2_rn(acc[i][j][0], acc[i][j][1]));
            uint32_t v1 = h2_bits(__floats2half2_rn(acc[i][j][2], acc[i][j][3]));
            *reinterpret_cast<uint32_t*>(g_Ph + (size_t)row0 * OUT_DIM + col) = v0;
            *reinterpret_cast<uint32_t*>(g_Ph + (size_t)(row0 + 8) * OUT_DIM + col) = v1;
        }
    }
}

// ---------------------------------------------------------------------------
// Fused LayerNorm + soft clamp, reading fp16 P (one uint4 = 8 halves/thread).
// tanh via saturating exp form: tanh(y) = 1 - 2/(e^{2y}+1).
// ---------------------------------------------------------------------------
__global__ __launch_bounds__(256)
void ln_tanh_kernel(const float* __restrict__ gamma,
                    const float* __restrict__ beta,
                    float* __restrict__ out) {
    const int row = blockIdx.x;
    const uint4* p4 = reinterpret_cast<const uint4*>(g_Ph + (size_t)row * OUT_DIM);

    uint4 pv = p4[threadIdx.x];
    float2 f0 = __half22float2(*reinterpret_cast<__half2*>(&pv.x));
    float2 f1 = __half22float2(*reinterpret_cast<__half2*>(&pv.y));
    float2 f2 = __half22float2(*reinterpret_cast<__half2*>(&pv.z));
    float2 f3 = __half22float2(*reinterpret_cast<__half2*>(&pv.w));
    float p[8] = {f0.x, f0.y, f1.x, f1.y, f2.x, f2.y, f3.x, f3.y};

    float sum = 0.0f, sq = 0.0f;
#pragma unroll
    for (int q = 0; q < 8; q++) { sum += p[q]; sq += p[q] * p[q]; }

#pragma unroll
    for (int off = 16; off > 0; off >>= 1) {
        sum += __shfl_xor_sync(0xFFFFFFFFu, sum, off);
        sq  += __shfl_xor_sync(0xFFFFFFFFu, sq,  off);
    }
    __shared__ float rs[8], rq[8];
    __shared__ float s_mu, s_inv;
    int lane = threadIdx.x & 31, wrp = threadIdx.x >> 5;
    if (lane == 0) { rs[wrp] = sum; rq[wrp] = sq; }
    __syncthreads();
    if (threadIdx.x == 0) {
        float ts = 0.0f, tq = 0.0f;
#pragma unroll
        for (int i = 0; i < 8; i++) { ts += rs[i]; tq += rq[i]; }
        float mu  = ts * (1.0f / OUT_DIM);
        float var = tq * (1.0f / OUT_DIM) - mu * mu;
        s_mu  = mu;
        s_inv = rsqrtf(fmaxf(var, 0.0f) + 1e-5f);
    }
    __syncthreads();
    const float mu = s_mu, inv = s_inv;

    const float4* g4 = reinterpret_cast<const float4*>(gamma);
    const float4* b4 = reinterpret_cast<const float4*>(beta);
    float4* o4 = reinterpret_cast<float4*>(out + (size_t)row * OUT_DIM);

#pragma unroll
    for (int it = 0; it < 2; it++) {
        int j4 = 2 * threadIdx.x + it;     // this thread's two float4 col-groups
        float4 gv = g4[j4];
        float4 bv = b4[j4];
        float ga[4] = {gv.x, gv.y, gv.z, gv.w};
        float ba[4] = {bv.x, bv.y, bv.z, bv.w};
        float* pp = &p[it * 4];
        float4 ov;
        float* oa = reinterpret_cast<float*>(&ov);
#pragma unroll
        for (int q = 0; q < 4; q++) {
            float nv = (pp[q] - mu) * inv * ga[q] + ba[q];
            // 5*tanh(nv/5) = 5*(1 - 2/(exp(0.4*nv)+1)); saturates correctly
            float e = __expf(0.4f * nv);
            oa[q] = 5.0f - 10.0f * __frcp_rn(e + 1.0f);
        }
        o4[j4] = ov;
    }
}

// ---------------------------------------------------------------------------
extern "C" void kernel_launch(void* const* d_in, const int* in_sizes, int n_in,
                              void* d_out, int out_size) {
    const float* x     = (const float*)d_in[0];
    const float* Wslow = (const float*)d_in[1];
    const float* Wmed  = (const float*)d_in[2];
    const float* Wfast = (const float*)d_in[3];
    const float* gamma = (const float*)d_in[4];
    const float* beta  = (const float*)d_in[5];
    float* out = (float*)d_out;

    // 1) Fused prepass (W-fold first, then x-convert)
    prep_kernel<<<6144, 256>>>(
        reinterpret_cast<const float4*>(x),
        reinterpret_cast<const float4*>(Wslow),
        reinterpret_cast<const float4*>(Wmed),
        reinterpret_cast<const float4*>(Wfast));

    // 2) Single fp16 mma.sync GEMM (fp16 epilogue), BK=64, 3 stages
    cudaFuncSetAttribute(gemm_fp16_kernel,
                         cudaFuncAttributeMaxDynamicSharedMemorySize,
                         SMEM_GEMM_BYTES);
    dim3 grid(B_ROWS / BM, OUT_DIM / BN, 1);
    gemm_fp16_kernel<<<grid, 256, SMEM_GEMM_BYTES>>>();

    // 3) Fused LayerNorm + fast tanh
    ln_tanh_kernel<<<B_ROWS, 256>>>(gamma, beta, out);
}

// round 8
// speedup vs baseline: 1.2401x; 1.2401x over previous
#include <cuda_runtime.h>
#include <cuda_fp16.h>
#include <cstdint>

#define B_ROWS  4096
#define IN_DIM  2048
#define OUT_DIM 2048

// ---------------------------------------------------------------------------
// Device scratch (static globals — no runtime allocation allowed)
// ---------------------------------------------------------------------------
__device__ __half g_Xh [(size_t)B_ROWS  * IN_DIM];   // half(clip(x,±5))        16MB
__device__ __half g_Wth[(size_t)OUT_DIM * IN_DIM];   // half(Ws+Wm+Wf)           8MB
__device__ __half g_Ph [(size_t)B_ROWS  * OUT_DIM];  // half(pre_act)           16MB

// ---------------------------------------------------------------------------
// PTX helpers (family-safe: cp.async, ldmatrix, mma.sync)
// ---------------------------------------------------------------------------
__device__ __forceinline__ uint32_t smem_u32(const void* p) {
    uint32_t a;
    asm("{ .reg .u64 t; cvta.to.shared.u64 t, %1; cvt.u32.u64 %0, t; }"
        : "=r"(a) : "l"(p));
    return a;
}

__device__ __forceinline__ uint32_t h2_bits(__half2 h) {
    return *reinterpret_cast<uint32_t*>(&h);
}

__device__ __forceinline__ void cp_async16(uint32_t dst, const void* src) {
    asm volatile("cp.async.cg.shared.global [%0], [%1], 16;"
                 :: "r"(dst), "l"(src));
}
#define CP_COMMIT() asm volatile("cp.async.commit_group;" ::: "memory")
#define CP_WAIT(n)  asm volatile("cp.async.wait_group %0;" :: "n"(n) : "memory")

#define LDSM_X4(r0, r1, r2, r3, addr)                                         \
    asm volatile("ldmatrix.sync.aligned.m8n8.x4.shared.b16 {%0,%1,%2,%3}, [%4];" \
                 : "=r"(r0), "=r"(r1), "=r"(r2), "=r"(r3) : "r"(addr))

#define MMA_16816(d0, d1, d2, d3, a0, a1, a2, a3, b0, b1)                     \
    asm volatile("mma.sync.aligned.m16n8k16.row.col.f32.f16.f16.f32 "         \
                 "{%0,%1,%2,%3}, {%4,%5,%6,%7}, {%8,%9}, {%0,%1,%2,%3};"      \
                 : "+f"(d0), "+f"(d1), "+f"(d2), "+f"(d3)                     \
                 : "r"(a0), "r"(a1), "r"(a2), "r"(a3), "r"(b0), "r"(b1))

// ---------------------------------------------------------------------------
// Fused prepass. Heavy W-fold blocks first (better tail behavior):
//   blocks [0, 2048)    : fold W_slow+W_medium+W_fast -> fp16
//   blocks [2048, 6144) : convert x (clip ±5 -> fp16)
// 8 elems/thread, 16B loads/stores.
// ---------------------------------------------------------------------------
__global__ void prep_kernel(const float4* __restrict__ x,
                            const float4* __restrict__ ws,
                            const float4* __restrict__ wm,
                            const float4* __restrict__ wf) {
    if (blockIdx.x < 2048) {
        int i = blockIdx.x * blockDim.x + threadIdx.x;
        float4 s0 = ws[2 * i], s1 = ws[2 * i + 1];
        float4 m0 = wm[2 * i], m1 = wm[2 * i + 1];
        float4 f0 = wf[2 * i], f1 = wf[2 * i + 1];
        uint4 ot;
        ot.x = h2_bits(__floats2half2_rn(s0.x + m0.x + f0.x, s0.y + m0.y + f0.y));
        ot.y = h2_bits(__floats2half2_rn(s0.z + m0.z + f0.z, s0.w + m0.w + f0.w));
        ot.z = h2_bits(__floats2half2_rn(s1.x + m1.x + f1.x, s1.y + m1.y + f1.y));
        ot.w = h2_bits(__floats2half2_rn(s1.z + m1.z + f1.z, s1.w + m1.w + f1.w));
        reinterpret_cast<uint4*>(g_Wth)[i] = ot;
    } else {
        int i = (blockIdx.x - 2048) * blockDim.x + threadIdx.x;
        float4 a = x[2 * i], b = x[2 * i + 1];
        a.x = fminf(fmaxf(a.x, -5.0f), 5.0f);  a.y = fminf(fmaxf(a.y, -5.0f), 5.0f);
        a.z = fminf(fmaxf(a.z, -5.0f), 5.0f);  a.w = fminf(fmaxf(a.w, -5.0f), 5.0f);
        b.x = fminf(fmaxf(b.x, -5.0f), 5.0f);  b.y = fminf(fmaxf(b.y, -5.0f), 5.0f);
        b.z = fminf(fmaxf(b.z, -5.0f), 5.0f);  b.w = fminf(fmaxf(b.w, -5.0f), 5.0f);
        uint4 o;
        o.x = h2_bits(__floats2half2_rn(a.x, a.y));
        o.y = h2_bits(__floats2half2_rn(a.z, a.w));
        o.z = h2_bits(__floats2half2_rn(b.x, b.y));
        o.w = h2_bits(__floats2half2_rn(b.z, b.w));
        reinterpret_cast<uint4*>(g_Xh)[i] = o;
    }
}

// ---------------------------------------------------------------------------
// fp16 mma.sync GEMM.  P[m,n] = sum_k A[m,k] * Wt[n,k]   (both K-major)
// CTA tile 128x128xK32, 8 warps as 2(m) x 4(n), warp tile 64x32.
// 5-stage cp.async pipeline (prefetch distance 4). Epilogue stores fp16 P.
// ---------------------------------------------------------------------------
constexpr int BM = 128, BN = 128, BK = 32, STAGES = 5;
constexpr int ASTRIDE = 40;                       // halves per smem row (80B, CF for ldmatrix)
constexpr int TILE_HALVES = 128 * ASTRIDE;        // 5120 (A or B tile)
constexpr int STG_HALVES  = 2 * TILE_HALVES;      // 10240
constexpr int SMEM_GEMM_BYTES = STAGES * STG_HALVES * 2;  // 102400
constexpr int NCHUNK = IN_DIM / BK;               // 64

__global__ __launch_bounds__(256, 2)
void gemm_fp16_kernel() {
    extern __shared__ __half sm[];
    const int tid  = threadIdx.x;
    const int wid  = tid >> 5;
    const int lane = tid & 31;
    const int bm = blockIdx.x * BM;
    const int bn = blockIdx.y * BN;
    const __half* __restrict__ W = g_Wth;

    const int wmBase = (wid & 1) * 64;   // warp m offset (2 warps)
    const int wnBase = (wid >> 1) * 32;  // warp n offset (4 warps)

    const uint32_t sbase = smem_u32(sm);

    // Per-thread load slots: q = 16B chunk within row, rows split across threads.
    const int lrow = tid >> 2;           // 0..63
    const int lq   = tid & 3;            // 0..3 (16B chunks of the 64B row)
    const __half* gA0 = g_Xh + (size_t)(bm + lrow) * IN_DIM + lq * 8;
    const __half* gA1 = g_Xh + (size_t)(bm + lrow + 64) * IN_DIM + lq * 8;
    const __half* gB0 = W    + (size_t)(bn + lrow) * IN_DIM + lq * 8;
    const __half* gB1 = W    + (size_t)(bn + lrow + 64) * IN_DIM + lq * 8;
    const uint32_t dA0 = (uint32_t)((lrow      ) * ASTRIDE + lq * 8) * 2;
    const uint32_t dA1 = (uint32_t)((lrow + 64 ) * ASTRIDE + lq * 8) * 2;
    const uint32_t dB0 = dA0 + TILE_HALVES * 2;
    const uint32_t dB1 = dA1 + TILE_HALVES * 2;

    auto load_stage = [&](int stage, int chunk) {
        const uint32_t sb = sbase + (uint32_t)stage * STG_HALVES * 2;
        const size_t ko = (size_t)chunk * BK;
        cp_async16(sb + dA0, gA0 + ko);
        cp_async16(sb + dA1, gA1 + ko);
        cp_async16(sb + dB0, gB0 + ko);
        cp_async16(sb + dB1, gB1 + ko);
    };

    // ldmatrix source addresses (lane-dependent, stage-relative)
    const int aRow = wmBase + (lane & 15);
    const int aCol = (lane >> 4) * 8;
    const int bRow = wnBase + (lane & 15);
    const uint32_t aOffBase = (uint32_t)(aRow * ASTRIDE + aCol) * 2;
    const uint32_t bOffBase = (uint32_t)(bRow * ASTRIDE + aCol) * 2 + TILE_HALVES * 2;

    float acc[4][4][4];
#pragma unroll
    for (int i = 0; i < 4; i++)
#pragma unroll
        for (int j = 0; j < 4; j++)
#pragma unroll
            for (int q = 0; q < 4; q++) acc[i][j][q] = 0.0f;

    // Prologue: chunks 0..3 into stages 0..3
#pragma unroll
    for (int s = 0; s < STAGES - 1; s++) {
        load_stage(s, s);
        CP_COMMIT();
    }

    int stage = 0;                        // stage holding chunk k
    int pstage = STAGES - 1;              // stage receiving the prefetch
#pragma unroll 1
    for (int k = 0; k < NCHUNK; k++) {
        CP_WAIT(STAGES - 2);
        __syncthreads();

        const int kn = k + STAGES - 1;
        if (kn < NCHUNK) load_stage(pstage, kn);
        CP_COMMIT();

        const uint32_t sb = sbase + (uint32_t)stage * STG_HALVES * 2;
        if (++stage == STAGES) stage = 0;
        if (++pstage == STAGES) pstage = 0;

#pragma unroll
        for (int kk = 0; kk < 2; kk++) {
            const uint32_t kOff = (uint32_t)(kk * 16) * 2;
            uint32_t a[4][4];
#pragma unroll
            for (int i = 0; i < 4; i++) {
                LDSM_X4(a[i][0], a[i][1], a[i][2], a[i][3],
                        sb + aOffBase + kOff + (uint32_t)(i * 16 * ASTRIDE) * 2);
            }
            uint32_t b[2][4];
#pragma unroll
            for (int jj = 0; jj < 2; jj++) {
                LDSM_X4(b[jj][0], b[jj][1], b[jj][2], b[jj][3],
                        sb + bOffBase + kOff + (uint32_t)(jj * 16 * ASTRIDE) * 2);
            }
#pragma unroll
            for (int i = 0; i < 4; i++) {
#pragma unroll
                for (int jj = 0; jj < 2; jj++) {
                    MMA_16816(acc[i][2 * jj][0], acc[i][2 * jj][1],
                              acc[i][2 * jj][2], acc[i][2 * jj][3],
                              a[i][0], a[i][1], a[i][2], a[i][3],
                              b[jj][0], b[jj][2]);
                    MMA_16816(acc[i][2 * jj + 1][0], acc[i][2 * jj + 1][1],
                              acc[i][2 * jj + 1][2], acc[i][2 * jj + 1][3],
                              a[i][0], a[i][1], a[i][2], a[i][3],
                              b[jj][1], b[jj][3]);
                }
            }
        }
    }

    // Epilogue: pack accumulators to fp16, 32-bit stores (cols even-aligned)
    const int er = lane >> 2;
    const int ec = (lane & 3) * 2;
#pragma unroll
    for (int i = 0; i < 4; i++) {
        const int row0 = bm + wmBase + i * 16 + er;
#pragma unroll
        for (int j = 0; j < 4; j++) {
            const int col = bn + wnBase + j * 8 + ec;
            uint32_t v0 = h2_bits(__floats2half2_rn(acc[i][j][0], acc[i][j][1]));
            uint32_t v1 = h2_bits(__floats2half2_rn(acc[i][j][2], acc[i][j][3]));
            *reinterpret_cast<uint32_t*>(g_Ph + (size_t)row0 * OUT_DIM + col) = v0;
            *reinterpret_cast<uint32_t*>(g_Ph + (size_t)(row0 + 8) * OUT_DIM + col) = v1;
        }
    }
}

// ---------------------------------------------------------------------------
// Fused LayerNorm + soft clamp, reading fp16 P (one uint4 = 8 halves/thread).
// tanh via saturating exp form: tanh(y) = 1 - 2/(e^{2y}+1).
// ---------------------------------------------------------------------------
__global__ __launch_bounds__(256)
void ln_tanh_kernel(const float* __restrict__ gamma,
                    const float* __restrict__ beta,
                    float* __restrict__ out) {
    const int row = blockIdx.x;
    const uint4* p4 = reinterpret_cast<const uint4*>(g_Ph + (size_t)row * OUT_DIM);

    uint4 pv = p4[threadIdx.x];
    float2 f0 = __half22float2(*reinterpret_cast<__half2*>(&pv.x));
    float2 f1 = __half22float2(*reinterpret_cast<__half2*>(&pv.y));
    float2 f2 = __half22float2(*reinterpret_cast<__half2*>(&pv.z));
    float2 f3 = __half22float2(*reinterpret_cast<__half2*>(&pv.w));
    float p[8] = {f0.x, f0.y, f1.x, f1.y, f2.x, f2.y, f3.x, f3.y};

    float sum = 0.0f, sq = 0.0f;
#pragma unroll
    for (int q = 0; q < 8; q++) { sum += p[q]; sq += p[q] * p[q]; }

#pragma unroll
    for (int off = 16; off > 0; off >>= 1) {
        sum += __shfl_xor_sync(0xFFFFFFFFu, sum, off);
        sq  += __shfl_xor_sync(0xFFFFFFFFu, sq,  off);
    }
    __shared__ float rs[8], rq[8];
    __shared__ float s_mu, s_inv;
    int lane = threadIdx.x & 31, wrp = threadIdx.x >> 5;
    if (lane == 0) { rs[wrp] = sum; rq[wrp] = sq; }
    __syncthreads();
    if (threadIdx.x == 0) {
        float ts = 0.0f, tq = 0.0f;
#pragma unroll
        for (int i = 0; i < 8; i++) { ts += rs[i]; tq += rq[i]; }
        float mu  = ts * (1.0f / OUT_DIM);
        float var = tq * (1.0f / OUT_DIM) - mu * mu;
        s_mu  = mu;
        s_inv = rsqrtf(fmaxf(var, 0.0f) + 1e-5f);
    }
    __syncthreads();
    const float mu = s_mu, inv = s_inv;

    const float4* g4 = reinterpret_cast<const float4*>(gamma);
    const float4* b4 = reinterpret_cast<const float4*>(beta);
    float4* o4 = reinterpret_cast<float4*>(out + (size_t)row * OUT_DIM);

#pragma unroll
    for (int it = 0; it < 2; it++) {
        int j4 = 2 * threadIdx.x + it;     // this thread's two float4 col-groups
        float4 gv = g4[j4];
        float4 bv = b4[j4];
        float ga[4] = {gv.x, gv.y, gv.z, gv.w};
        float ba[4] = {bv.x, bv.y, bv.z, bv.w};
        float* pp = &p[it * 4];
        float4 ov;
        float* oa = reinterpret_cast<float*>(&ov);
#pragma unroll
        for (int q = 0; q < 4; q++) {
            float nv = (pp[q] - mu) * inv * ga[q] + ba[q];
            // 5*tanh(nv/5) = 5*(1 - 2/(exp(0.4*nv)+1)); saturates correctly
            float e = __expf(0.4f * nv);
            oa[q] = 5.0f - 10.0f * __frcp_rn(e + 1.0f);
        }
        o4[j4] = ov;
    }
}

// ---------------------------------------------------------------------------
extern "C" void kernel_launch(void* const* d_in, const int* in_sizes, int n_in,
                              void* d_out, int out_size) {
    const float* x     = (const float*)d_in[0];
    const float* Wslow = (const float*)d_in[1];
    const float* Wmed  = (const float*)d_in[2];
    const float* Wfast = (const float*)d_in[3];
    const float* gamma = (const float*)d_in[4];
    const float* beta  = (const float*)d_in[5];
    float* out = (float*)d_out;

    // 1) Fused prepass (W-fold first, then x-convert)
    prep_kernel<<<6144, 256>>>(
        reinterpret_cast<const float4*>(x),
        reinterpret_cast<const float4*>(Wslow),
        reinterpret_cast<const float4*>(Wmed),
        reinterpret_cast<const float4*>(Wfast));

    // 2) Single fp16 mma.sync GEMM (fp16 epilogue), BK=32, 5 stages
    cudaFuncSetAttribute(gemm_fp16_kernel,
                         cudaFuncAttributeMaxDynamicSharedMemorySize,
                         SMEM_GEMM_BYTES);
    dim3 grid(B_ROWS / BM, OUT_DIM / BN, 1);
    gemm_fp16_kernel<<<grid, 256, SMEM_GEMM_BYTES>>>();

    // 3) Fused LayerNorm + fast tanh
    ln_tanh_kernel<<<B_ROWS, 256>>>(gamma, beta, out);
}